// round 8
// baseline (speedup 1.0000x reference)
#include <cuda_runtime.h>
#include <cuda_bf16.h>
#include <math.h>
#include <stdint.h>

// ---------------- problem constants ----------------
#define Bq   8
#define SPq  800
#define SSq  48
#define NTq  848
#define DPq  2048
#define DSq  1024
#define DCq  1024
#define Hq   8
#define HDq  256
#define FPq  16384
#define FSq  4096
#define EPSq 1e-6f
#define MASKV (-2.3819763e+38f)

static constexpr size_t NPROW = (size_t)Bq * SPq;   // 6400
static constexpr size_t NSROW = (size_t)Bq * SSq;   // 384

// ---------------- scratch layout ----------------
static constexpr size_t O_HP   = 0;
static constexpr size_t O_HS   = O_HP   + NPROW * DPq;
static constexpr size_t O_MOD1 = O_HS   + NSROW * DSq;
static constexpr size_t O_MOD2 = O_MOD1 + (size_t)Bq * 3 * DSq;
static constexpr size_t O_QP   = O_MOD2 + (size_t)Bq * 3 * DSq;
static constexpr size_t O_QS   = O_QP   + NPROW * (size_t)(Hq*HDq);
static constexpr size_t O_KP   = O_QS   + NSROW * (size_t)(Hq*HDq);
static constexpr size_t O_KS   = O_KP   + NPROW * HDq;
static constexpr size_t O_VP   = O_KS   + NSROW * HDq;
static constexpr size_t O_VS   = O_VP   + NPROW * HDq;
static constexpr size_t O_Q    = O_VS   + NSROW * HDq;
static constexpr size_t O_K    = O_Q    + (size_t)Bq*Hq*NTq*HDq;
static constexpr size_t O_VT   = O_K    + (size_t)Bq*NTq*HDq;
static constexpr size_t O_SC   = O_VT   + (size_t)Bq*NTq*HDq;
static constexpr size_t O_AP   = O_SC   + (size_t)Bq*Hq*NTq*NTq;
static constexpr size_t O_AS   = O_AP   + NPROW * (size_t)(Hq*HDq);
static constexpr size_t O_RESP = O_AS   + NSROW * (size_t)(Hq*HDq);
static constexpr size_t O_HP2  = O_RESP + NPROW * DPq;
static constexpr size_t O_RESS = O_HP2  + NPROW * DPq;
static constexpr size_t O_H2S  = O_RESS + NSROW * DSq;
static constexpr size_t O_UP   = O_H2S  + NSROW * DSq;
static constexpr size_t O_HPM  = O_UP   + NPROW * FPq;
static constexpr size_t O_US   = O_HPM  + NPROW * FPq;
static constexpr size_t O_HSM  = O_US   + NSROW * FSq;
static constexpr size_t SCR_TOTAL = O_HSM + NSROW * FSq;

__device__ float g_scr[SCR_TOTAL];

// ---------------- helpers ----------------
__device__ __forceinline__ uint32_t smem_u32(const void* p) {
    uint32_t a;
    asm("{ .reg .u64 t; cvta.to.shared.u64 t, %1; cvt.u32.u64 %0, t; }" : "=r"(a) : "l"(p));
    return a;
}
__device__ __forceinline__ void sts_v2(uint32_t addr, uint32_t x, uint32_t y) {
    asm volatile("st.shared.v2.b32 [%0], {%1, %2};" :: "r"(addr), "r"(x), "r"(y) : "memory");
}

#define LDM_X4(R, addr) \
    asm volatile("ldmatrix.sync.aligned.m8n8.x4.shared.b16 {%0,%1,%2,%3}, [%4];" \
        : "=r"((R)[0]), "=r"((R)[1]), "=r"((R)[2]), "=r"((R)[3]) : "r"(addr))

__device__ __forceinline__ float gelu_tanh(float x) {
    float x3 = x * x * x;
    return 0.5f * x * (1.0f + tanhf(0.7978845608028654f * (x + 0.044715f * x3)));
}

// split float pair into packed bf16 hi and lo
__device__ __forceinline__ void split2(float x, float y, uint32_t& hi, uint32_t& lo) {
    __nv_bfloat16 hx = __float2bfloat16_rn(x);
    __nv_bfloat16 hy = __float2bfloat16_rn(y);
    float rx = x - __bfloat162float(hx);
    float ry = y - __bfloat162float(hy);
    __nv_bfloat16 lx = __float2bfloat16_rn(rx);
    __nv_bfloat16 ly = __float2bfloat16_rn(ry);
    hi = (uint32_t)__bfloat16_as_ushort(hx) | ((uint32_t)__bfloat16_as_ushort(hy) << 16);
    lo = (uint32_t)__bfloat16_as_ushort(lx) | ((uint32_t)__bfloat16_as_ushort(ly) << 16);
}

#define MMA_BF16(d, a, b) \
    asm volatile("mma.sync.aligned.m16n8k16.row.col.f32.bf16.bf16.f32 " \
        "{%0,%1,%2,%3}, {%4,%5,%6,%7}, {%8,%9}, {%0,%1,%2,%3};" \
        : "+f"((d)[0]), "+f"((d)[1]), "+f"((d)[2]), "+f"((d)[3]) \
        : "r"((a)[0]), "r"((a)[1]), "r"((a)[2]), "r"((a)[3]), "r"((b)[0]), "r"((b)[1]))

struct EpiParams {
    const float* resid;
    const float* gate;
    const float* umat;
    float* outp;
    float* outs;
    float scale;
    int ldg;
    int rpb;
};

// ---------------- mma.sync bf16x3 NT GEMM: C[M,N] = A[M,K] @ B[N,K]^T --------
// Block tile 128x128x32, 8 warps (4 m x 2 n), warp tile 32x64. ldmatrix frags.
#define SROW 80                     // bytes per padded row (40 bf16)
#define SUB  (128 * SROW)           // 10240 B
#define OFF_AH 0
#define OFF_AL (1 * SUB)
#define OFF_BH (2 * SUB)
#define OFF_BL (3 * SUB)
#define SLOT   (4 * SUB)            // 40960 B
#define MM_SMEM (2 * SLOT)          // 81920 B

// Modes: 0 plain; 1 scale+mask; 2 PV scatter; 4 +resid; 5 resid+acc*gate; 6 gelu*U
template <int MODE>
__global__ void __launch_bounds__(256, 1) mgemm(
    const float* __restrict__ Ag, const float* __restrict__ Bg,
    float* __restrict__ Cg, int M, int N, int K,
    long long sAz, long long sBz, int bDivB, long long sCz, EpiParams ep)
{
    extern __shared__ char smem_raw[];
    uint32_t sbase = smem_u32(smem_raw);

    int tid = threadIdx.x;
    int wid = tid >> 5, lane = tid & 31;
    int g = lane >> 2, t4 = lane & 3;
    int wm = wid & 3, wn = wid >> 2;          // wm 0..3, wn 0..1
    int z = blockIdx.z;
    const float* A = Ag + (size_t)z * (size_t)sAz;
    const float* B = Bg + (size_t)(z / bDivB) * (size_t)sBz;
    int m0 = blockIdx.y * 128;
    int n0 = blockIdx.x * 128;

    // staging coordinates
    int srow = tid >> 3;            // base row (advance 32/iter)
    int sq   = tid & 7;             // float4 index within 32-float row

    // lane-invariant ldmatrix offsets
    uint32_t aoff = (uint32_t)((wm * 32 + (lane & 15)) * SROW + (lane >> 4) * 16);
    uint32_t boff = (uint32_t)((wn * 64 + ((lane & 7) | ((lane >> 4) << 3))) * SROW
                               + ((lane >> 3) & 1) * 16);

    float acc[2][8][4];
#pragma unroll
    for (int a = 0; a < 2; a++)
#pragma unroll
        for (int b = 0; b < 8; b++)
#pragma unroll
            for (int c = 0; c < 4; c++) acc[a][b][c] = 0.0f;

    float4 pa[4], pb[4];
    int nc = (K + 31) / 32;

    auto load_chunk = [&](int c) {
        int k0 = c * 32;
        int gk = k0 + sq * 4;
        bool kok = (gk < K);
#pragma unroll
        for (int it = 0; it < 4; ++it) {
            int row = srow + it * 32;
            int gr = m0 + row;
            pa[it] = (kok && gr < M) ? *reinterpret_cast<const float4*>(A + (size_t)gr * K + gk)
                                     : make_float4(0.f, 0.f, 0.f, 0.f);
            int gn = n0 + row;
            pb[it] = (kok && gn < N) ? *reinterpret_cast<const float4*>(B + (size_t)gn * K + gk)
                                     : make_float4(0.f, 0.f, 0.f, 0.f);
        }
    };
    auto store_chunk = [&](int slot) {
        uint32_t sb = sbase + slot * SLOT;
#pragma unroll
        for (int it = 0; it < 4; ++it) {
            int row = srow + it * 32;
            uint32_t off = (uint32_t)(row * SROW + sq * 8);
            uint32_t h0, l0, h1, l1;
            split2(pa[it].x, pa[it].y, h0, l0);
            split2(pa[it].z, pa[it].w, h1, l1);
            sts_v2(sb + OFF_AH + off, h0, h1);
            sts_v2(sb + OFF_AL + off, l0, l1);
            split2(pb[it].x, pb[it].y, h0, l0);
            split2(pb[it].z, pb[it].w, h1, l1);
            sts_v2(sb + OFF_BH + off, h0, h1);
            sts_v2(sb + OFF_BL + off, l0, l1);
        }
    };

    load_chunk(0);
    store_chunk(0);
    __syncthreads();

    for (int c = 0; c < nc; ++c) {
        bool more = (c + 1 < nc);
        if (more) load_chunk(c + 1);

        uint32_t sb = sbase + (c & 1) * SLOT;
#pragma unroll
        for (int kk = 0; kk < 2; ++kk) {
            uint32_t kByte = (uint32_t)(kk * 32);
            uint32_t ah[2][4], al[2][4], bb[8][2];
            // A hi (2 x ldmatrix.x4)
            LDM_X4(ah[0], sb + OFF_AH + kByte + aoff);
            LDM_X4(ah[1], sb + OFF_AH + kByte + aoff + 16 * SROW);
            // B hi (4 x ldmatrix.x4 -> 8 fragments)
#pragma unroll
            for (int jp = 0; jp < 4; ++jp)
                LDM_X4(&bb[2 * jp][0], sb + OFF_BH + kByte + boff + (uint32_t)(jp * 16 * SROW));
#pragma unroll
            for (int mt = 0; mt < 2; ++mt)
#pragma unroll
                for (int j = 0; j < 8; ++j) MMA_BF16(acc[mt][j], ah[mt], bb[j]);
            // A lo
            LDM_X4(al[0], sb + OFF_AL + kByte + aoff);
            LDM_X4(al[1], sb + OFF_AL + kByte + aoff + 16 * SROW);
#pragma unroll
            for (int mt = 0; mt < 2; ++mt)
#pragma unroll
                for (int j = 0; j < 8; ++j) MMA_BF16(acc[mt][j], al[mt], bb[j]);
            // B lo (overwrite bb)
#pragma unroll
            for (int jp = 0; jp < 4; ++jp)
                LDM_X4(&bb[2 * jp][0], sb + OFF_BL + kByte + boff + (uint32_t)(jp * 16 * SROW));
#pragma unroll
            for (int mt = 0; mt < 2; ++mt)
#pragma unroll
                for (int j = 0; j < 8; ++j) MMA_BF16(acc[mt][j], ah[mt], bb[j]);

            // overlap next-chunk conversion+STS with second kk MMA block
            if (kk == 0 && more) store_chunk((c + 1) & 1);
        }
        __syncthreads();
    }

    // ---------------- epilogue (accumulators in registers) ----------------
#pragma unroll
    for (int mt = 0; mt < 2; ++mt) {
#pragma unroll
        for (int half = 0; half < 2; ++half) {
            int r = m0 + wm * 32 + mt * 16 + g + half * 8;
            if (r >= M) continue;
#pragma unroll
            for (int j = 0; j < 8; ++j) {
                int cc = n0 + wn * 64 + j * 8 + t4 * 2;
                if (cc >= N) continue;
                float v0 = acc[mt][j][half * 2 + 0];
                float v1 = acc[mt][j][half * 2 + 1];
                size_t idx = (size_t)r * N + cc;
                if constexpr (MODE == 0) {
                    *reinterpret_cast<float2*>(Cg + (size_t)z * sCz + idx) = make_float2(v0, v1);
                } else if constexpr (MODE == 1) {
                    float m0v = (r < SPq && cc >= SPq) ? MASKV : 0.0f;
                    float m1v = (r < SPq && cc + 1 >= SPq) ? MASKV : 0.0f;
                    *reinterpret_cast<float2*>(Cg + (size_t)z * sCz + idx) =
                        make_float2(v0 * ep.scale + m0v, v1 * ep.scale + m1v);
                } else if constexpr (MODE == 2) {
                    int b_ = z / bDivB, h_ = z % bDivB;
                    float* dst = (r < SPq)
                        ? ep.outp + ((size_t)b_ * SPq + r) * (Hq * HDq) + h_ * HDq + cc
                        : ep.outs + ((size_t)b_ * SSq + (r - SPq)) * (Hq * HDq) + h_ * HDq + cc;
                    *reinterpret_cast<float2*>(dst) = make_float2(v0, v1);
                } else if constexpr (MODE == 4) {
                    float2 rs = *reinterpret_cast<const float2*>(ep.resid + idx);
                    *reinterpret_cast<float2*>(Cg + idx) = make_float2(rs.x + v0, rs.y + v1);
                } else if constexpr (MODE == 5) {
                    float2 rs = *reinterpret_cast<const float2*>(ep.resid + idx);
                    const float* gt = ep.gate + (size_t)(r / ep.rpb) * ep.ldg + cc;
                    *reinterpret_cast<float2*>(Cg + idx) =
                        make_float2(rs.x + v0 * gt[0], rs.y + v1 * gt[1]);
                } else if constexpr (MODE == 6) {
                    float2 um = *reinterpret_cast<const float2*>(ep.umat + idx);
                    *reinterpret_cast<float2*>(Cg + idx) =
                        make_float2(gelu_tanh(v0) * um.x, gelu_tanh(v1) * um.y);
                }
            }
        }
    }
}

// ---------------- small SIMT GEMM for cond modulation (M=8) -----------------
__global__ void __launch_bounds__(256) gemm_bias(
    const float* __restrict__ A, const float* __restrict__ B,
    const float* __restrict__ bias, float* __restrict__ C, int M, int N, int K)
{
    __shared__ float As[8][128];
    __shared__ float Bs[8][128];
    int m0 = blockIdx.y * 128, n0 = blockIdx.x * 128;
    int tid = threadIdx.x, tx = tid & 15, ty = tid >> 4;
    int ldRow = tid >> 1, ldCol = (tid & 1) * 4;
    float acc[8][8];
#pragma unroll
    for (int i = 0; i < 8; i++)
#pragma unroll
        for (int j = 0; j < 8; j++) acc[i][j] = 0.0f;
    for (int k0 = 0; k0 < K; k0 += 8) {
        float4 av = make_float4(0.f, 0.f, 0.f, 0.f);
        if (m0 + ldRow < M) av = *reinterpret_cast<const float4*>(A + (size_t)(m0 + ldRow) * K + k0 + ldCol);
        As[ldCol + 0][ldRow] = av.x; As[ldCol + 1][ldRow] = av.y;
        As[ldCol + 2][ldRow] = av.z; As[ldCol + 3][ldRow] = av.w;
        float4 bv = make_float4(0.f, 0.f, 0.f, 0.f);
        if (n0 + ldRow < N) bv = *reinterpret_cast<const float4*>(B + (size_t)(n0 + ldRow) * K + k0 + ldCol);
        Bs[ldCol + 0][ldRow] = bv.x; Bs[ldCol + 1][ldRow] = bv.y;
        Bs[ldCol + 2][ldRow] = bv.z; Bs[ldCol + 3][ldRow] = bv.w;
        __syncthreads();
#pragma unroll
        for (int kk = 0; kk < 8; kk++) {
            float a[8], b[8];
#pragma unroll
            for (int i = 0; i < 8; i++) a[i] = As[kk][ty * 8 + i];
#pragma unroll
            for (int j = 0; j < 8; j++) b[j] = Bs[kk][tx * 8 + j];
#pragma unroll
            for (int i = 0; i < 8; i++)
#pragma unroll
                for (int j = 0; j < 8; j++) acc[i][j] += a[i] * b[j];
        }
        __syncthreads();
    }
#pragma unroll
    for (int i = 0; i < 8; i++) {
        int r = m0 + ty * 8 + i;
        if (r >= M) continue;
#pragma unroll
        for (int j = 0; j < 8; j++) {
            int c = n0 + tx * 8 + j;
            if (c >= N) continue;
            C[(size_t)r * N + c] = acc[i][j] + bias[c];
        }
    }
}

// ---------------- norms ----------------
__global__ void rmsnorm_gemma_k(const float* __restrict__ x, const float* __restrict__ w,
                                float* __restrict__ out, int D)
{
    int row = blockIdx.x;
    const float* xr = x + (size_t)row * D;
    float ss = 0.0f;
    for (int c = threadIdx.x; c < D; c += 256) { float v = xr[c]; ss += v * v; }
    __shared__ float red[256];
    red[threadIdx.x] = ss; __syncthreads();
    for (int s = 128; s > 0; s >>= 1) {
        if (threadIdx.x < s) red[threadIdx.x] += red[threadIdx.x + s];
        __syncthreads();
    }
    float rinv = rsqrtf(red[0] / (float)D + EPSq);
    float* orow = out + (size_t)row * D;
    for (int c = threadIdx.x; c < D; c += 256)
        orow[c] = xr[c] * rinv * (1.0f + w[c]);
}

__global__ void ada_norm_k(const float* __restrict__ x, const float* __restrict__ mod,
                           float* __restrict__ out, int D, int rowsPerB)
{
    int row = blockIdx.x;
    int b = row / rowsPerB;
    const float* xr = x + (size_t)row * D;
    float ss = 0.0f;
    for (int c = threadIdx.x; c < D; c += 256) { float v = xr[c]; ss += v * v; }
    __shared__ float red[256];
    red[threadIdx.x] = ss; __syncthreads();
    for (int s = 128; s > 0; s >>= 1) {
        if (threadIdx.x < s) red[threadIdx.x] += red[threadIdx.x + s];
        __syncthreads();
    }
    float rinv = rsqrtf(red[0] / (float)D + EPSq);
    const float* mb = mod + (size_t)b * 3 * D;
    float* orow = out + (size_t)row * D;
    for (int c = threadIdx.x; c < D; c += 256) {
        float scale = mb[c], shift = mb[D + c];
        orow[c] = xr[c] * rinv * (1.0f + scale) + shift;
    }
}

// ---------------- rope / transpose ----------------
__global__ void rope_q_k(const float* __restrict__ qp, const float* __restrict__ qs,
                         float* __restrict__ q)
{
    size_t idx = (size_t)blockIdx.x * blockDim.x + threadIdx.x;
    const size_t total = (size_t)Bq * NTq * Hq * (HDq / 2);
    if (idx >= total) return;
    int d = (int)(idx % (HDq / 2)); size_t t = idx / (HDq / 2);
    int h = (int)(t % Hq); t /= Hq;
    int n = (int)(t % NTq); int b = (int)(t / NTq);
    const float* src = (n < SPq)
        ? qp + ((size_t)b * SPq + n) * (Hq * HDq) + h * HDq
        : qs + ((size_t)b * SSq + (n - SPq)) * (Hq * HDq) + h * HDq;
    float x1 = src[d], x2 = src[d + 128];
    float invf = powf(10000.0f, -(float)d * (1.0f / 128.0f));
    float ang = (float)n * invf;
    float cs = cosf(ang), sn = sinf(ang);
    float* dst = q + (((size_t)b * Hq + h) * NTq + n) * HDq;
    dst[d] = x1 * cs - x2 * sn;
    dst[d + 128] = x2 * cs + x1 * sn;
}

__global__ void rope_k_k(const float* __restrict__ kp, const float* __restrict__ ks,
                         float* __restrict__ k)
{
    size_t idx = (size_t)blockIdx.x * blockDim.x + threadIdx.x;
    const size_t total = (size_t)Bq * NTq * (HDq / 2);
    if (idx >= total) return;
    int d = (int)(idx % (HDq / 2)); size_t t = idx / (HDq / 2);
    int n = (int)(t % NTq); int b = (int)(t / NTq);
    const float* src = (n < SPq)
        ? kp + ((size_t)b * SPq + n) * HDq
        : ks + ((size_t)b * SSq + (n - SPq)) * HDq;
    float x1 = src[d], x2 = src[d + 128];
    float invf = powf(10000.0f, -(float)d * (1.0f / 128.0f));
    float ang = (float)n * invf;
    float cs = cosf(ang), sn = sinf(ang);
    float* dst = k + ((size_t)b * NTq + n) * HDq;
    dst[d] = x1 * cs - x2 * sn;
    dst[d + 128] = x2 * cs + x1 * sn;
}

__global__ void transpose_v_k(const float* __restrict__ vp, const float* __restrict__ vs,
                              float* __restrict__ vt)
{
    size_t idx = (size_t)blockIdx.x * blockDim.x + threadIdx.x;
    const size_t total = (size_t)Bq * NTq * HDq;
    if (idx >= total) return;
    int d = (int)(idx % HDq); size_t t = idx / HDq;
    int n = (int)(t % NTq); int b = (int)(t / NTq);
    float v = (n < SPq)
        ? vp[((size_t)b * SPq + n) * HDq + d]
        : vs[((size_t)b * SSq + (n - SPq)) * HDq + d];
    vt[((size_t)b * HDq + d) * NTq + n] = v;
}

// ---------------- softmax ----------------
__global__ void softmax_k(float* __restrict__ s, int L)
{
    float* row = s + (size_t)blockIdx.x * L;
    __shared__ float red[256];
    float mx = -INFINITY;
    for (int c = threadIdx.x; c < L; c += 256) mx = fmaxf(mx, row[c]);
    red[threadIdx.x] = mx; __syncthreads();
    for (int st = 128; st > 0; st >>= 1) {
        if (threadIdx.x < st) red[threadIdx.x] = fmaxf(red[threadIdx.x], red[threadIdx.x + st]);
        __syncthreads();
    }
    mx = red[0]; __syncthreads();
    float sum = 0.0f;
    for (int c = threadIdx.x; c < L; c += 256) {
        float e = expf(row[c] - mx);
        row[c] = e; sum += e;
    }
    red[threadIdx.x] = sum; __syncthreads();
    for (int st = 128; st > 0; st >>= 1) {
        if (threadIdx.x < st) red[threadIdx.x] += red[threadIdx.x + st];
        __syncthreads();
    }
    float inv = 1.0f / red[0];
    for (int c = threadIdx.x; c < L; c += 256) row[c] *= inv;
}

// ---------------- host-side dispatch ----------------
static void run_mm(int mode, const float* A, const float* B, float* C,
                   int M, int N, int K,
                   long long sAz, long long sBz, int bDivB, long long sCz,
                   int Z, EpiParams ep)
{
    dim3 grid((N + 127) / 128, (M + 127) / 128, Z);
    switch (mode) {
        case 0:
            cudaFuncSetAttribute(mgemm<0>, cudaFuncAttributeMaxDynamicSharedMemorySize, MM_SMEM);
            mgemm<0><<<grid, 256, MM_SMEM>>>(A, B, C, M, N, K, sAz, sBz, bDivB, sCz, ep); break;
        case 1:
            cudaFuncSetAttribute(mgemm<1>, cudaFuncAttributeMaxDynamicSharedMemorySize, MM_SMEM);
            mgemm<1><<<grid, 256, MM_SMEM>>>(A, B, C, M, N, K, sAz, sBz, bDivB, sCz, ep); break;
        case 2:
            cudaFuncSetAttribute(mgemm<2>, cudaFuncAttributeMaxDynamicSharedMemorySize, MM_SMEM);
            mgemm<2><<<grid, 256, MM_SMEM>>>(A, B, C, M, N, K, sAz, sBz, bDivB, sCz, ep); break;
        case 4:
            cudaFuncSetAttribute(mgemm<4>, cudaFuncAttributeMaxDynamicSharedMemorySize, MM_SMEM);
            mgemm<4><<<grid, 256, MM_SMEM>>>(A, B, C, M, N, K, sAz, sBz, bDivB, sCz, ep); break;
        case 5:
            cudaFuncSetAttribute(mgemm<5>, cudaFuncAttributeMaxDynamicSharedMemorySize, MM_SMEM);
            mgemm<5><<<grid, 256, MM_SMEM>>>(A, B, C, M, N, K, sAz, sBz, bDivB, sCz, ep); break;
        case 6:
            cudaFuncSetAttribute(mgemm<6>, cudaFuncAttributeMaxDynamicSharedMemorySize, MM_SMEM);
            mgemm<6><<<grid, 256, MM_SMEM>>>(A, B, C, M, N, K, sAz, sBz, bDivB, sCz, ep); break;
    }
}

extern "C" void kernel_launch(void* const* d_in, const int* in_sizes, int n_in,
                              void* d_out, int out_size)
{
    const float* prefix_x    = (const float*)d_in[0];
    const float* suffix_x    = (const float*)d_in[1];
    const float* cond        = (const float*)d_in[2];
    const float* p_ln_w      = (const float*)d_in[3];
    const float* p_q_w       = (const float*)d_in[4];
    const float* p_k_w       = (const float*)d_in[5];
    const float* p_v_w       = (const float*)d_in[6];
    const float* p_o_w       = (const float*)d_in[7];
    const float* p_post_ln_w = (const float*)d_in[8];
    const float* p_gate_w    = (const float*)d_in[9];
    const float* p_up_w      = (const float*)d_in[10];
    const float* p_down_w    = (const float*)d_in[11];
    const float* s_ada1_w    = (const float*)d_in[12];
    const float* s_ada1_b    = (const float*)d_in[13];
    const float* s_q_w       = (const float*)d_in[14];
    const float* s_k_w       = (const float*)d_in[15];
    const float* s_v_w       = (const float*)d_in[16];
    const float* s_o_w       = (const float*)d_in[17];
    const float* s_ada2_w    = (const float*)d_in[18];
    const float* s_ada2_b    = (const float*)d_in[19];
    const float* s_gate_w    = (const float*)d_in[20];
    const float* s_up_w      = (const float*)d_in[21];
    const float* s_down_w    = (const float*)d_in[22];

    float* scr = nullptr;
    cudaGetSymbolAddress((void**)&scr, g_scr);

    float* hp    = scr + O_HP;
    float* hs    = scr + O_HS;
    float* mod1  = scr + O_MOD1;
    float* mod2  = scr + O_MOD2;
    float* qp    = scr + O_QP;
    float* qs    = scr + O_QS;
    float* kp    = scr + O_KP;
    float* ks    = scr + O_KS;
    float* vp    = scr + O_VP;
    float* vs    = scr + O_VS;
    float* q     = scr + O_Q;
    float* k     = scr + O_K;
    float* vt    = scr + O_VT;
    float* sc    = scr + O_SC;
    float* ap    = scr + O_AP;
    float* as_   = scr + O_AS;
    float* res_p = scr + O_RESP;
    float* hp2   = scr + O_HP2;
    float* res_s = scr + O_RESS;
    float* h2s   = scr + O_H2S;
    float* Up    = scr + O_UP;
    float* Hp    = scr + O_HPM;
    float* Us    = scr + O_US;
    float* Hs    = scr + O_HSM;

    float* outp = (float*)d_out;
    float* outs = outp + NPROW * DPq;

    EpiParams ep0 = {};

    // 1) norms + ada modulation
    rmsnorm_gemma_k<<<(int)NPROW, 256>>>(prefix_x, p_ln_w, hp, DPq);
    gemm_bias<<<dim3(24, 1, 1), 256>>>(cond, s_ada1_w, s_ada1_b, mod1, Bq, 3 * DSq, DCq);
    ada_norm_k<<<(int)NSROW, 256>>>(suffix_x, mod1, hs, DSq, SSq);

    // 2) QKV projections
    run_mm(0, hp, p_q_w, qp, (int)NPROW, Hq * HDq, DPq, 0, 0, 1, 0, 1, ep0);
    run_mm(0, hp, p_k_w, kp, (int)NPROW, HDq,      DPq, 0, 0, 1, 0, 1, ep0);
    run_mm(0, hp, p_v_w, vp, (int)NPROW, HDq,      DPq, 0, 0, 1, 0, 1, ep0);
    run_mm(0, hs, s_q_w, qs, (int)NSROW, Hq * HDq, DSq, 0, 0, 1, 0, 1, ep0);
    run_mm(0, hs, s_k_w, ks, (int)NSROW, HDq,      DSq, 0, 0, 1, 0, 1, ep0);
    run_mm(0, hs, s_v_w, vs, (int)NSROW, HDq,      DSq, 0, 0, 1, 0, 1, ep0);

    // 3) RoPE + layouts
    {
        size_t tq = (size_t)Bq * NTq * Hq * (HDq / 2);
        rope_q_k<<<(int)((tq + 255) / 256), 256>>>(qp, qs, q);
        size_t tk = (size_t)Bq * NTq * (HDq / 2);
        rope_k_k<<<(int)((tk + 255) / 256), 256>>>(kp, ks, k);
        size_t tv = (size_t)Bq * NTq * HDq;
        transpose_v_k<<<(int)((tv + 255) / 256), 256>>>(vp, vs, vt);
    }

    // 4) attention
    { EpiParams e = ep0; e.scale = 0.0625f;
      run_mm(1, q, k, sc, NTq, NTq, HDq,
             (long long)NTq * HDq, (long long)NTq * HDq, Hq,
             (long long)NTq * NTq, Bq * Hq, e); }
    softmax_k<<<Bq * Hq * NTq, 256>>>(sc, NTq);
    { EpiParams e = ep0; e.outp = ap; e.outs = as_;
      run_mm(2, sc, vt, nullptr, NTq, HDq, NTq,
             (long long)NTq * NTq, (long long)HDq * NTq, Hq, 0, Bq * Hq, e); }

    // 5) prefix: o-proj + residual, post-norm, MLP
    { EpiParams e = ep0; e.resid = prefix_x;
      run_mm(4, ap, p_o_w, res_p, (int)NPROW, DPq, Hq * HDq, 0, 0, 1, 0, 1, e); }
    rmsnorm_gemma_k<<<(int)NPROW, 256>>>(res_p, p_post_ln_w, hp2, DPq);
    run_mm(0, hp2, p_up_w, Up, (int)NPROW, FPq, DPq, 0, 0, 1, 0, 1, ep0);
    { EpiParams e = ep0; e.umat = Up;
      run_mm(6, hp2, p_gate_w, Hp, (int)NPROW, FPq, DPq, 0, 0, 1, 0, 1, e); }
    { EpiParams e = ep0; e.resid = res_p;
      run_mm(4, Hp, p_down_w, outp, (int)NPROW, DPq, FPq, 0, 0, 1, 0, 1, e); }

    // 6) suffix: gated o-proj + residual, ada-norm2, gated MLP
    { EpiParams e = ep0; e.resid = suffix_x; e.gate = mod1 + 2 * DSq; e.ldg = 3 * DSq; e.rpb = SSq;
      run_mm(5, as_, s_o_w, res_s, (int)NSROW, DSq, Hq * HDq, 0, 0, 1, 0, 1, e); }
    gemm_bias<<<dim3(24, 1, 1), 256>>>(cond, s_ada2_w, s_ada2_b, mod2, Bq, 3 * DSq, DCq);
    ada_norm_k<<<(int)NSROW, 256>>>(res_s, mod2, h2s, DSq, SSq);
    run_mm(0, h2s, s_up_w, Us, (int)NSROW, FSq, DSq, 0, 0, 1, 0, 1, ep0);
    { EpiParams e = ep0; e.umat = Us;
      run_mm(6, h2s, s_gate_w, Hs, (int)NSROW, FSq, DSq, 0, 0, 1, 0, 1, e); }
    { EpiParams e = ep0; e.resid = res_s; e.gate = mod2 + 2 * DSq; e.ldg = 3 * DSq; e.rpb = SSq;
      run_mm(5, Hs, s_down_w, outs, (int)NSROW, DSq, FSq, 0, 0, 1, 0, 1, e); }
}

// round 12
// speedup vs baseline: 1.4711x; 1.4711x over previous
#include <cuda_runtime.h>
#include <cuda_bf16.h>
#include <math.h>
#include <stdint.h>

// ---------------- problem constants ----------------
#define Bq   8
#define SPq  800
#define SSq  48
#define NTq  848
#define DPq  2048
#define DSq  1024
#define DCq  1024
#define Hq   8
#define HDq  256
#define FPq  16384
#define FSq  4096
#define EPSq 1e-6f
#define MASKV (-2.3819763e+38f)

static constexpr size_t NPROW = (size_t)Bq * SPq;   // 6400
static constexpr size_t NSROW = (size_t)Bq * SSq;   // 384

// ---------------- f32 scratch ----------------
static constexpr size_t O_MOD1 = 0;
static constexpr size_t O_MOD2 = O_MOD1 + (size_t)Bq * 3 * DSq;
static constexpr size_t O_QP   = O_MOD2 + (size_t)Bq * 3 * DSq;
static constexpr size_t O_QS   = O_QP   + NPROW * (size_t)(Hq*HDq);
static constexpr size_t O_KP   = O_QS   + NSROW * (size_t)(Hq*HDq);
static constexpr size_t O_KS   = O_KP   + NPROW * HDq;
static constexpr size_t O_VP   = O_KS   + NSROW * HDq;
static constexpr size_t O_VS   = O_VP   + NPROW * HDq;
static constexpr size_t O_SCF  = O_VS   + NSROW * HDq;                    // scores f32 (exp scratch)
static constexpr size_t O_UPF  = O_SCF  + (size_t)Bq*Hq*NTq*NTq;          // Up f32
static constexpr size_t O_USF  = O_UPF  + NPROW * FPq;
static constexpr size_t O_RESP = O_USF  + NSROW * FSq;
static constexpr size_t O_RESS = O_RESP + NPROW * DPq;
static constexpr size_t F32_TOTAL = O_RESS + NSROW * DSq;

__device__ float g_scr[F32_TOTAL];

// ---------------- bf16 scratch (hi set + lo set) ----------------
static constexpr size_t B_HP   = 0;                                       // norm(prefix) [6400,2048]
static constexpr size_t B_HS   = B_HP  + NPROW * DPq;                     // [384,1024]
static constexpr size_t B_Q    = B_HS  + NSROW * DSq;                     // [64,848,256]
static constexpr size_t B_K    = B_Q   + (size_t)Bq*Hq*NTq*HDq;           // [8,848,256]
static constexpr size_t B_VT   = B_K   + (size_t)Bq*NTq*HDq;              // [8,256,848]
static constexpr size_t B_SC   = B_VT  + (size_t)Bq*NTq*HDq;              // [64,848,848]
static constexpr size_t B_AP   = B_SC  + (size_t)Bq*Hq*NTq*NTq;           // [6400,2048]
static constexpr size_t B_AS   = B_AP  + NPROW * (size_t)(Hq*HDq);        // [384,2048]
static constexpr size_t B_HP2  = B_AS  + NSROW * (size_t)(Hq*HDq);        // [6400,2048]
static constexpr size_t B_HPM  = B_HP2 + NPROW * DPq;                     // [6400,16384]
static constexpr size_t B_H2S  = B_HPM + NPROW * FPq;                     // [384,1024]
static constexpr size_t B_HSM  = B_H2S + NSROW * DSq;                     // [384,4096]
static constexpr size_t B_WPQ  = B_HSM + NSROW * FSq;
static constexpr size_t B_WPK  = B_WPQ + (size_t)(Hq*HDq)*DPq;
static constexpr size_t B_WPV  = B_WPK + (size_t)HDq*DPq;
static constexpr size_t B_WPO  = B_WPV + (size_t)HDq*DPq;
static constexpr size_t B_WPG  = B_WPO + (size_t)DPq*(Hq*HDq);
static constexpr size_t B_WPU  = B_WPG + (size_t)FPq*DPq;
static constexpr size_t B_WPD  = B_WPU + (size_t)FPq*DPq;
static constexpr size_t B_WSQ  = B_WPD + (size_t)DPq*FPq;
static constexpr size_t B_WSK  = B_WSQ + (size_t)(Hq*HDq)*DSq;
static constexpr size_t B_WSV  = B_WSK + (size_t)HDq*DSq;
static constexpr size_t B_WSO  = B_WSV + (size_t)HDq*DSq;
static constexpr size_t B_WSG  = B_WSO + (size_t)DSq*(Hq*HDq);
static constexpr size_t B_WSU  = B_WSG + (size_t)FSq*DSq;
static constexpr size_t B_WSD  = B_WSU + (size_t)FSq*DSq;
static constexpr size_t SET_TOTAL = B_WSD + (size_t)DSq*FSq;

__device__ __nv_bfloat16 g_scrh[2 * SET_TOTAL];

// ---------------- helpers ----------------
__device__ __forceinline__ uint32_t smem_u32(const void* p) {
    uint32_t a;
    asm("{ .reg .u64 t; cvta.to.shared.u64 t, %1; cvt.u32.u64 %0, t; }" : "=r"(a) : "l"(p));
    return a;
}
#define LDM_X4(R, addr) \
    asm volatile("ldmatrix.sync.aligned.m8n8.x4.shared.b16 {%0,%1,%2,%3}, [%4];" \
        : "=r"((R)[0]), "=r"((R)[1]), "=r"((R)[2]), "=r"((R)[3]) : "r"(addr))
#define CP_A16(dst, src, sz) \
    asm volatile("cp.async.cg.shared.global [%0], [%1], 16, %2;" \
        :: "r"(dst), "l"(src), "r"(sz) : "memory")
#define CP_COMMIT() asm volatile("cp.async.commit_group;" ::: "memory")
#define CP_WAIT1()  asm volatile("cp.async.wait_group 1;" ::: "memory")

__device__ __forceinline__ float gelu_tanh(float x) {
    float x3 = x * x * x;
    return 0.5f * x * (1.0f + tanhf(0.7978845608028654f * (x + 0.044715f * x3)));
}
__device__ __forceinline__ void split2(float x, float y, uint32_t& hi, uint32_t& lo) {
    __nv_bfloat16 hx = __float2bfloat16_rn(x);
    __nv_bfloat16 hy = __float2bfloat16_rn(y);
    float rx = x - __bfloat162float(hx);
    float ry = y - __bfloat162float(hy);
    __nv_bfloat16 lx = __float2bfloat16_rn(rx);
    __nv_bfloat16 ly = __float2bfloat16_rn(ry);
    hi = (uint32_t)__bfloat16_as_ushort(hx) | ((uint32_t)__bfloat16_as_ushort(hy) << 16);
    lo = (uint32_t)__bfloat16_as_ushort(lx) | ((uint32_t)__bfloat16_as_ushort(ly) << 16);
}
__device__ __forceinline__ void emit1(__nv_bfloat16* h, __nv_bfloat16* l, size_t off, float v) {
    __nv_bfloat16 hv = __float2bfloat16_rn(v);
    h[off] = hv;
    l[off] = __float2bfloat16_rn(v - __bfloat162float(hv));
}

#define MMA_BF16(d, a, b) \
    asm volatile("mma.sync.aligned.m16n8k16.row.col.f32.bf16.bf16.f32 " \
        "{%0,%1,%2,%3}, {%4,%5,%6,%7}, {%8,%9}, {%0,%1,%2,%3};" \
        : "+f"((d)[0]), "+f"((d)[1]), "+f"((d)[2]), "+f"((d)[3]) \
        : "r"((a)[0]), "r"((a)[1]), "r"((a)[2]), "r"((a)[3]), "r"((b)[0]), "r"((b)[1]))

struct EpiParams {
    const float* resid;
    const float* gate;
    const float* umat;
    __nv_bfloat16 *h0, *l0, *h1, *l1;   // split outputs (mode 2: prefix/suffix; mode 6: h0/l0)
    float scale;
    int ldg;
    int rpb;
};

// ---------------- bf16x3 NT GEMM, cp.async staged, 2 CTAs/SM ----------------
// C[M,N] = A[M,K] @ B[N,K]^T with A,B pre-split (hi,lo) bf16. Tile 128x128x32.
#define SROW 80                      // padded row bytes (32 bf16 data + pad)
#define SUB  (128 * SROW)            // 10240
#define OFF_AH 0
#define OFF_AL (1 * SUB)
#define OFF_BH (2 * SUB)
#define OFF_BL (3 * SUB)
#define SLOT   (4 * SUB)             // 40960
#define MM_SMEM (2 * SLOT)           // 81920 -> 2 CTAs/SM

// Modes: 0 plain f32; 1 scale+mask f32; 2 PV scatter hi/lo; 4 +resid f32;
//        5 resid+acc*gate f32; 6 gelu(acc)*U -> hi/lo
template <int MODE>
__global__ void __launch_bounds__(256, 2) mgemm(
    const __nv_bfloat16* __restrict__ AgH, const __nv_bfloat16* __restrict__ AgL,
    const __nv_bfloat16* __restrict__ BgH, const __nv_bfloat16* __restrict__ BgL,
    float* __restrict__ Cg, int M, int N, int K,
    long long sAz, long long sBz, int bDivB, long long sCz, EpiParams ep)
{
    extern __shared__ char smem_raw[];
    uint32_t sbase = smem_u32(smem_raw);

    int tid = threadIdx.x;
    int wid = tid >> 5, lane = tid & 31;
    int g = lane >> 2, t4 = lane & 3;
    int wm = wid & 3, wn = wid >> 2;
    int z = blockIdx.z;
    const __nv_bfloat16* Ah = AgH + (size_t)z * (size_t)sAz;
    const __nv_bfloat16* Al = AgL + (size_t)z * (size_t)sAz;
    const __nv_bfloat16* Bh = BgH + (size_t)(z / bDivB) * (size_t)sBz;
    const __nv_bfloat16* Bl = BgL + (size_t)(z / bDivB) * (size_t)sBz;
    int m0 = blockIdx.y * 128;
    int n0 = blockIdx.x * 128;

    // ldmatrix offsets (same scheme as validated R8 kernel)
    uint32_t aoff = (uint32_t)((wm * 32 + (lane & 15)) * SROW + (lane >> 4) * 16);
    uint32_t boff = (uint32_t)((wn * 64 + ((lane & 7) | ((lane >> 4) << 3))) * SROW
                               + ((lane >> 3) & 1) * 16);

    float acc[2][8][4];
#pragma unroll
    for (int a = 0; a < 2; a++)
#pragma unroll
        for (int b = 0; b < 8; b++)
#pragma unroll
            for (int c = 0; c < 4; c++) acc[a][b][c] = 0.0f;

    int nc = (K + 31) / 32;

    auto issue = [&](int c) {
        uint32_t sb = sbase + (c & 1) * SLOT;
        int k0 = c * 32;
#pragma unroll
        for (int it = 0; it < 2; ++it) {
            int ci = it * 256 + tid;                // 0..511
            int row = ci >> 2, cq = ci & 3;
            int kk = k0 + cq * 8;
            bool kv = kk < K;
            uint32_t dst = sb + (uint32_t)(row * SROW + cq * 16);
            int gr = m0 + row;
            bool okA = kv && (gr < M);
            const __nv_bfloat16* sA = okA ? (Ah + (size_t)gr * K + kk) : Ah;
            const __nv_bfloat16* sAl = okA ? (Al + (size_t)gr * K + kk) : Al;
            CP_A16(dst + OFF_AH, sA, okA ? 16 : 0);
            CP_A16(dst + OFF_AL, sAl, okA ? 16 : 0);
            int gn = n0 + row;
            bool okB = kv && (gn < N);
            const __nv_bfloat16* sB = okB ? (Bh + (size_t)gn * K + kk) : Bh;
            const __nv_bfloat16* sBl = okB ? (Bl + (size_t)gn * K + kk) : Bl;
            CP_A16(dst + OFF_BH, sB, okB ? 16 : 0);
            CP_A16(dst + OFF_BL, sBl, okB ? 16 : 0);
        }
    };

    issue(0); CP_COMMIT();
    if (nc > 1) issue(1);
    CP_COMMIT();

    for (int c = 0; c < nc; ++c) {
        CP_WAIT1();
        __syncthreads();
        uint32_t sb = sbase + (c & 1) * SLOT;
#pragma unroll
        for (int kk = 0; kk < 2; ++kk) {
            uint32_t kByte = (uint32_t)(kk * 32);
            uint32_t ah[2][4], al[2][4], bb[8][2];
            LDM_X4(ah[0], sb + OFF_AH + kByte + aoff);
            LDM_X4(ah[1], sb + OFF_AH + kByte + aoff + 16 * SROW);
#pragma unroll
            for (int jp = 0; jp < 4; ++jp)
                LDM_X4(&bb[2 * jp][0], sb + OFF_BH + kByte + boff + (uint32_t)(jp * 16 * SROW));
#pragma unroll
            for (int mt = 0; mt < 2; ++mt)
#pragma unroll
                for (int j = 0; j < 8; ++j) MMA_BF16(acc[mt][j], ah[mt], bb[j]);
            LDM_X4(al[0], sb + OFF_AL + kByte + aoff);
            LDM_X4(al[1], sb + OFF_AL + kByte + aoff + 16 * SROW);
#pragma unroll
            for (int mt = 0; mt < 2; ++mt)
#pragma unroll
                for (int j = 0; j < 8; ++j) MMA_BF16(acc[mt][j], al[mt], bb[j]);
#pragma unroll
            for (int jp = 0; jp < 4; ++jp)
                LDM_X4(&bb[2 * jp][0], sb + OFF_BL + kByte + boff + (uint32_t)(jp * 16 * SROW));
#pragma unroll
            for (int mt = 0; mt < 2; ++mt)
#pragma unroll
                for (int j = 0; j < 8; ++j) MMA_BF16(acc[mt][j], ah[mt], bb[j]);
        }
        __syncthreads();
        if (c + 2 < nc) issue(c + 2);
        CP_COMMIT();
    }

    // ---------------- epilogue ----------------
#pragma unroll
    for (int mt = 0; mt < 2; ++mt) {
#pragma unroll
        for (int half = 0; half < 2; ++half) {
            int r = m0 + wm * 32 + mt * 16 + g + half * 8;
            if (r >= M) continue;
#pragma unroll
            for (int j = 0; j < 8; ++j) {
                int cc = n0 + wn * 64 + j * 8 + t4 * 2;
                if (cc >= N) continue;
                float v0 = acc[mt][j][half * 2 + 0];
                float v1 = acc[mt][j][half * 2 + 1];
                size_t idx = (size_t)r * N + cc;
                if constexpr (MODE == 0) {
                    *reinterpret_cast<float2*>(Cg + (size_t)z * sCz + idx) = make_float2(v0, v1);
                } else if constexpr (MODE == 1) {
                    float m0v = (r < SPq && cc >= SPq) ? MASKV : 0.0f;
                    float m1v = (r < SPq && cc + 1 >= SPq) ? MASKV : 0.0f;
                    *reinterpret_cast<float2*>(Cg + (size_t)z * sCz + idx) =
                        make_float2(v0 * ep.scale + m0v, v1 * ep.scale + m1v);
                } else if constexpr (MODE == 2) {
                    int b_ = z / bDivB, h_ = z % bDivB;
                    uint32_t hi, lo;
                    split2(v0, v1, hi, lo);
                    size_t off = (r < SPq)
                        ? ((size_t)b_ * SPq + r) * (Hq * HDq) + h_ * HDq + cc
                        : ((size_t)b_ * SSq + (r - SPq)) * (Hq * HDq) + h_ * HDq + cc;
                    __nv_bfloat16* dh = (r < SPq) ? ep.h0 : ep.h1;
                    __nv_bfloat16* dl = (r < SPq) ? ep.l0 : ep.l1;
                    *reinterpret_cast<uint32_t*>(dh + off) = hi;
                    *reinterpret_cast<uint32_t*>(dl + off) = lo;
                } else if constexpr (MODE == 4) {
                    float2 rs = *reinterpret_cast<const float2*>(ep.resid + idx);
                    *reinterpret_cast<float2*>(Cg + idx) = make_float2(rs.x + v0, rs.y + v1);
                } else if constexpr (MODE == 5) {
                    float2 rs = *reinterpret_cast<const float2*>(ep.resid + idx);
                    const float* gt = ep.gate + (size_t)(r / ep.rpb) * ep.ldg + cc;
                    *reinterpret_cast<float2*>(Cg + idx) =
                        make_float2(rs.x + v0 * gt[0], rs.y + v1 * gt[1]);
                } else if constexpr (MODE == 6) {
                    float2 um = *reinterpret_cast<const float2*>(ep.umat + idx);
                    float g0 = gelu_tanh(v0) * um.x;
                    float g1 = gelu_tanh(v1) * um.y;
                    uint32_t hi, lo;
                    split2(g0, g1, hi, lo);
                    *reinterpret_cast<uint32_t*>(ep.h0 + idx) = hi;
                    *reinterpret_cast<uint32_t*>(ep.l0 + idx) = lo;
                }
            }
        }
    }
}

// ---------------- weight split (f32 -> bf16 hi/lo) ----------------
__global__ void split_arr(const float* __restrict__ s, __nv_bfloat16* __restrict__ h,
                          __nv_bfloat16* __restrict__ l, size_t n)
{
    size_t i = ((size_t)blockIdx.x * 256 + threadIdx.x) * 4;
    if (i >= n) return;
    float4 v = *reinterpret_cast<const float4*>(s + i);
    uint32_t h0, l0, h1, l1;
    split2(v.x, v.y, h0, l0);
    split2(v.z, v.w, h1, l1);
    *reinterpret_cast<uint2*>(h + i) = make_uint2(h0, h1);
    *reinterpret_cast<uint2*>(l + i) = make_uint2(l0, l1);
}

// ---------------- small SIMT GEMM for cond modulation (M=8) -----------------
__global__ void __launch_bounds__(256) gemm_bias(
    const float* __restrict__ A, const float* __restrict__ B,
    const float* __restrict__ bias, float* __restrict__ C, int M, int N, int K)
{
    __shared__ float As[8][128];
    __shared__ float Bs[8][128];
    int m0 = blockIdx.y * 128, n0 = blockIdx.x * 128;
    int tid = threadIdx.x, tx = tid & 15, ty = tid >> 4;
    int ldRow = tid >> 1, ldCol = (tid & 1) * 4;
    float acc[8][8];
#pragma unroll
    for (int i = 0; i < 8; i++)
#pragma unroll
        for (int j = 0; j < 8; j++) acc[i][j] = 0.0f;
    for (int k0 = 0; k0 < K; k0 += 8) {
        float4 av = make_float4(0.f, 0.f, 0.f, 0.f);
        if (m0 + ldRow < M) av = *reinterpret_cast<const float4*>(A + (size_t)(m0 + ldRow) * K + k0 + ldCol);
        As[ldCol + 0][ldRow] = av.x; As[ldCol + 1][ldRow] = av.y;
        As[ldCol + 2][ldRow] = av.z; As[ldCol + 3][ldRow] = av.w;
        float4 bv = make_float4(0.f, 0.f, 0.f, 0.f);
        if (n0 + ldRow < N) bv = *reinterpret_cast<const float4*>(B + (size_t)(n0 + ldRow) * K + k0 + ldCol);
        Bs[ldCol + 0][ldRow] = bv.x; Bs[ldCol + 1][ldRow] = bv.y;
        Bs[ldCol + 2][ldRow] = bv.z; Bs[ldCol + 3][ldRow] = bv.w;
        __syncthreads();
#pragma unroll
        for (int kk = 0; kk < 8; kk++) {
            float a[8], b[8];
#pragma unroll
            for (int i = 0; i < 8; i++) a[i] = As[kk][ty * 8 + i];
#pragma unroll
            for (int j = 0; j < 8; j++) b[j] = Bs[kk][tx * 8 + j];
#pragma unroll
            for (int i = 0; i < 8; i++)
#pragma unroll
                for (int j = 0; j < 8; j++) acc[i][j] += a[i] * b[j];
        }
        __syncthreads();
    }
#pragma unroll
    for (int i = 0; i < 8; i++) {
        int r = m0 + ty * 8 + i;
        if (r >= M) continue;
#pragma unroll
        for (int j = 0; j < 8; j++) {
            int c = n0 + tx * 8 + j;
            if (c >= N) continue;
            C[(size_t)r * N + c] = acc[i][j] + bias[c];
        }
    }
}

// ---------------- norms (emit bf16 hi/lo) ----------------
__global__ void rmsnorm_split_k(const float* __restrict__ x, const float* __restrict__ w,
                                __nv_bfloat16* __restrict__ oh, __nv_bfloat16* __restrict__ ol, int D)
{
    int row = blockIdx.x;
    const float* xr = x + (size_t)row * D;
    float ss = 0.0f;
    for (int c = threadIdx.x; c < D; c += 256) { float v = xr[c]; ss += v * v; }
    __shared__ float red[256];
    red[threadIdx.x] = ss; __syncthreads();
    for (int s = 128; s > 0; s >>= 1) {
        if (threadIdx.x < s) red[threadIdx.x] += red[threadIdx.x + s];
        __syncthreads();
    }
    float rinv = rsqrtf(red[0] / (float)D + EPSq);
    size_t base = (size_t)row * D;
    for (int c = threadIdx.x * 2; c < D; c += 512) {
        float v0 = xr[c] * rinv * (1.0f + w[c]);
        float v1 = xr[c + 1] * rinv * (1.0f + w[c + 1]);
        uint32_t hi, lo;
        split2(v0, v1, hi, lo);
        *reinterpret_cast<uint32_t*>(oh + base + c) = hi;
        *reinterpret_cast<uint32_t*>(ol + base + c) = lo;
    }
}

__global__ void ada_norm_split_k(const float* __restrict__ x, const float* __restrict__ mod,
                                 __nv_bfloat16* __restrict__ oh, __nv_bfloat16* __restrict__ ol,
                                 int D, int rowsPerB)
{
    int row = blockIdx.x;
    int b = row / rowsPerB;
    const float* xr = x + (size_t)row * D;
    float ss = 0.0f;
    for (int c = threadIdx.x; c < D; c += 256) { float v = xr[c]; ss += v * v; }
    __shared__ float red[256];
    red[threadIdx.x] = ss; __syncthreads();
    for (int s = 128; s > 0; s >>= 1) {
        if (threadIdx.x < s) red[threadIdx.x] += red[threadIdx.x + s];
        __syncthreads();
    }
    float rinv = rsqrtf(red[0] / (float)D + EPSq);
    const float* mb = mod + (size_t)b * 3 * D;
    size_t base = (size_t)row * D;
    for (int c = threadIdx.x * 2; c < D; c += 512) {
        float v0 = xr[c] * rinv * (1.0f + mb[c]) + mb[D + c];
        float v1 = xr[c + 1] * rinv * (1.0f + mb[c + 1]) + mb[D + c + 1];
        uint32_t hi, lo;
        split2(v0, v1, hi, lo);
        *reinterpret_cast<uint32_t*>(oh + base + c) = hi;
        *reinterpret_cast<uint32_t*>(ol + base + c) = lo;
    }
}

// ---------------- rope / transpose (emit hi/lo) ----------------
__global__ void rope_q_k(const float* __restrict__ qp, const float* __restrict__ qs,
                         __nv_bfloat16* __restrict__ qh, __nv_bfloat16* __restrict__ ql)
{
    size_t idx = (size_t)blockIdx.x * blockDim.x + threadIdx.x;
    const size_t total = (size_t)Bq * NTq * Hq * (HDq / 2);
    if (idx >= total) return;
    int d = (int)(idx % (HDq / 2)); size_t t = idx / (HDq / 2);
    int h = (int)(t % Hq); t /= Hq;
    int n = (int)(t % NTq); int b = (int)(t / NTq);
    const float* src = (n < SPq)
        ? qp + ((size_t)b * SPq + n) * (Hq * HDq) + h * HDq
        : qs + ((size_t)b * SSq + (n - SPq)) * (Hq * HDq) + h * HDq;
    float x1 = src[d], x2 = src[d + 128];
    float invf = powf(10000.0f, -(float)d * (1.0f / 128.0f));
    float ang = (float)n * invf;
    float cs = cosf(ang), sn = sinf(ang);
    size_t dst = (((size_t)b * Hq + h) * NTq + n) * HDq;
    emit1(qh, ql, dst + d, x1 * cs - x2 * sn);
    emit1(qh, ql, dst + d + 128, x2 * cs + x1 * sn);
}

__global__ void rope_k_k(const float* __restrict__ kp, const float* __restrict__ ks,
                         __nv_bfloat16* __restrict__ kh, __nv_bfloat16* __restrict__ kl)
{
    size_t idx = (size_t)blockIdx.x * blockDim.x + threadIdx.x;
    const size_t total = (size_t)Bq * NTq * (HDq / 2);
    if (idx >= total) return;
    int d = (int)(idx % (HDq / 2)); size_t t = idx / (HDq / 2);
    int n = (int)(t % NTq); int b = (int)(t / NTq);
    const float* src = (n < SPq)
        ? kp + ((size_t)b * SPq + n) * HDq
        : ks + ((size_t)b * SSq + (n - SPq)) * HDq;
    float x1 = src[d], x2 = src[d + 128];
    float invf = powf(10000.0f, -(float)d * (1.0f / 128.0f));
    float ang = (float)n * invf;
    float cs = cosf(ang), sn = sinf(ang);
    size_t dst = ((size_t)b * NTq + n) * HDq;
    emit1(kh, kl, dst + d, x1 * cs - x2 * sn);
    emit1(kh, kl, dst + d + 128, x2 * cs + x1 * sn);
}

__global__ void transpose_v_k(const float* __restrict__ vp, const float* __restrict__ vs,
                              __nv_bfloat16* __restrict__ vh, __nv_bfloat16* __restrict__ vl)
{
    size_t idx = (size_t)blockIdx.x * blockDim.x + threadIdx.x;
    const size_t total = (size_t)Bq * NTq * HDq;
    if (idx >= total) return;
    int d = (int)(idx % HDq); size_t t = idx / HDq;
    int n = (int)(t % NTq); int b = (int)(t / NTq);
    float v = (n < SPq)
        ? vp[((size_t)b * SPq + n) * HDq + d]
        : vs[((size_t)b * SSq + (n - SPq)) * HDq + d];
    emit1(vh, vl, ((size_t)b * HDq + d) * NTq + n, v);
}

// ---------------- softmax (emit hi/lo) ----------------
__global__ void softmax_split_k(float* __restrict__ s, __nv_bfloat16* __restrict__ oh,
                                __nv_bfloat16* __restrict__ ol, int L)
{
    float* row = s + (size_t)blockIdx.x * L;
    __shared__ float red[256];
    float mx = -INFINITY;
    for (int c = threadIdx.x; c < L; c += 256) mx = fmaxf(mx, row[c]);
    red[threadIdx.x] = mx; __syncthreads();
    for (int st = 128; st > 0; st >>= 1) {
        if (threadIdx.x < st) red[threadIdx.x] = fmaxf(red[threadIdx.x], red[threadIdx.x + st]);
        __syncthreads();
    }
    mx = red[0]; __syncthreads();
    float sum = 0.0f;
    for (int c = threadIdx.x; c < L; c += 256) {
        float e = expf(row[c] - mx);
        row[c] = e; sum += e;
    }
    red[threadIdx.x] = sum; __syncthreads();
    for (int st = 128; st > 0; st >>= 1) {
        if (threadIdx.x < st) red[threadIdx.x] += red[threadIdx.x + st];
        __syncthreads();
    }
    float inv = 1.0f / red[0];
    size_t base = (size_t)blockIdx.x * L;
    for (int c = threadIdx.x * 2; c < L; c += 512) {
        float v0 = row[c] * inv;
        float v1 = row[c + 1] * inv;
        uint32_t hi, lo;
        split2(v0, v1, hi, lo);
        *reinterpret_cast<uint32_t*>(oh + base + c) = hi;
        *reinterpret_cast<uint32_t*>(ol + base + c) = lo;
    }
}

// ---------------- host-side dispatch ----------------
typedef __nv_bfloat16 bf16;

static void run_mm(int mode, const bf16* Ah, const bf16* Al, const bf16* Bh, const bf16* Bl,
                   float* C, int M, int N, int K,
                   long long sAz, long long sBz, int bDivB, long long sCz,
                   int Z, EpiParams ep)
{
    dim3 grid((N + 127) / 128, (M + 127) / 128, Z);
    switch (mode) {
        case 0:
            cudaFuncSetAttribute(mgemm<0>, cudaFuncAttributeMaxDynamicSharedMemorySize, MM_SMEM);
            mgemm<0><<<grid, 256, MM_SMEM>>>(Ah, Al, Bh, Bl, C, M, N, K, sAz, sBz, bDivB, sCz, ep); break;
        case 1:
            cudaFuncSetAttribute(mgemm<1>, cudaFuncAttributeMaxDynamicSharedMemorySize, MM_SMEM);
            mgemm<1><<<grid, 256, MM_SMEM>>>(Ah, Al, Bh, Bl, C, M, N, K, sAz, sBz, bDivB, sCz, ep); break;
        case 2:
            cudaFuncSetAttribute(mgemm<2>, cudaFuncAttributeMaxDynamicSharedMemorySize, MM_SMEM);
            mgemm<2><<<grid, 256, MM_SMEM>>>(Ah, Al, Bh, Bl, C, M, N, K, sAz, sBz, bDivB, sCz, ep); break;
        case 4:
            cudaFuncSetAttribute(mgemm<4>, cudaFuncAttributeMaxDynamicSharedMemorySize, MM_SMEM);
            mgemm<4><<<grid, 256, MM_SMEM>>>(Ah, Al, Bh, Bl, C, M, N, K, sAz, sBz, bDivB, sCz, ep); break;
        case 5:
            cudaFuncSetAttribute(mgemm<5>, cudaFuncAttributeMaxDynamicSharedMemorySize, MM_SMEM);
            mgemm<5><<<grid, 256, MM_SMEM>>>(Ah, Al, Bh, Bl, C, M, N, K, sAz, sBz, bDivB, sCz, ep); break;
        case 6:
            cudaFuncSetAttribute(mgemm<6>, cudaFuncAttributeMaxDynamicSharedMemorySize, MM_SMEM);
            mgemm<6><<<grid, 256, MM_SMEM>>>(Ah, Al, Bh, Bl, C, M, N, K, sAz, sBz, bDivB, sCz, ep); break;
    }
}

static void do_split(const float* s, bf16* h, bf16* l, size_t n)
{
    int blocks = (int)((n / 4 + 255) / 256);
    split_arr<<<blocks, 256>>>(s, h, l, n);
}

extern "C" void kernel_launch(void* const* d_in, const int* in_sizes, int n_in,
                              void* d_out, int out_size)
{
    const float* prefix_x    = (const float*)d_in[0];
    const float* suffix_x    = (const float*)d_in[1];
    const float* cond        = (const float*)d_in[2];
    const float* p_ln_w      = (const float*)d_in[3];
    const float* p_q_w       = (const float*)d_in[4];
    const float* p_k_w       = (const float*)d_in[5];
    const float* p_v_w       = (const float*)d_in[6];
    const float* p_o_w       = (const float*)d_in[7];
    const float* p_post_ln_w = (const float*)d_in[8];
    const float* p_gate_w    = (const float*)d_in[9];
    const float* p_up_w      = (const float*)d_in[10];
    const float* p_down_w    = (const float*)d_in[11];
    const float* s_ada1_w    = (const float*)d_in[12];
    const float* s_ada1_b    = (const float*)d_in[13];
    const float* s_q_w       = (const float*)d_in[14];
    const float* s_k_w       = (const float*)d_in[15];
    const float* s_v_w       = (const float*)d_in[16];
    const float* s_o_w       = (const float*)d_in[17];
    const float* s_ada2_w    = (const float*)d_in[18];
    const float* s_ada2_b    = (const float*)d_in[19];
    const float* s_gate_w    = (const float*)d_in[20];
    const float* s_up_w      = (const float*)d_in[21];
    const float* s_down_w    = (const float*)d_in[22];

    float* scr = nullptr;
    cudaGetSymbolAddress((void**)&scr, g_scr);
    bf16* sh = nullptr;
    cudaGetSymbolAddress((void**)&sh, g_scrh);
    bf16* sl = sh + SET_TOTAL;

    float* mod1  = scr + O_MOD1;
    float* mod2  = scr + O_MOD2;
    float* qp    = scr + O_QP;
    float* qs    = scr + O_QS;
    float* kp    = scr + O_KP;
    float* ks    = scr + O_KS;
    float* vp    = scr + O_VP;
    float* vs    = scr + O_VS;
    float* sc    = scr + O_SCF;
    float* Up    = scr + O_UPF;
    float* Us    = scr + O_USF;
    float* res_p = scr + O_RESP;
    float* res_s = scr + O_RESS;

    float* outp = (float*)d_out;
    float* outs = outp + NPROW * DPq;

    EpiParams ep0 = {};

    // 0) weight splits
    do_split(p_q_w,    sh + B_WPQ, sl + B_WPQ, (size_t)(Hq*HDq)*DPq);
    do_split(p_k_w,    sh + B_WPK, sl + B_WPK, (size_t)HDq*DPq);
    do_split(p_v_w,    sh + B_WPV, sl + B_WPV, (size_t)HDq*DPq);
    do_split(p_o_w,    sh + B_WPO, sl + B_WPO, (size_t)DPq*(Hq*HDq));
    do_split(p_gate_w, sh + B_WPG, sl + B_WPG, (size_t)FPq*DPq);
    do_split(p_up_w,   sh + B_WPU, sl + B_WPU, (size_t)FPq*DPq);
    do_split(p_down_w, sh + B_WPD, sl + B_WPD, (size_t)DPq*FPq);
    do_split(s_q_w,    sh + B_WSQ, sl + B_WSQ, (size_t)(Hq*HDq)*DSq);
    do_split(s_k_w,    sh + B_WSK, sl + B_WSK, (size_t)HDq*DSq);
    do_split(s_v_w,    sh + B_WSV, sl + B_WSV, (size_t)HDq*DSq);
    do_split(s_o_w,    sh + B_WSO, sl + B_WSO, (size_t)DSq*(Hq*HDq));
    do_split(s_gate_w, sh + B_WSG, sl + B_WSG, (size_t)FSq*DSq);
    do_split(s_up_w,   sh + B_WSU, sl + B_WSU, (size_t)FSq*DSq);
    do_split(s_down_w, sh + B_WSD, sl + B_WSD, (size_t)DSq*FSq);

    // 1) norms + ada modulation
    rmsnorm_split_k<<<(int)NPROW, 256>>>(prefix_x, p_ln_w, sh + B_HP, sl + B_HP, DPq);
    gemm_bias<<<dim3(24, 1, 1), 256>>>(cond, s_ada1_w, s_ada1_b, mod1, Bq, 3 * DSq, DCq);
    ada_norm_split_k<<<(int)NSROW, 256>>>(suffix_x, mod1, sh + B_HS, sl + B_HS, DSq, SSq);

    // 2) QKV projections (f32 out, consumed by rope/transpose)
    run_mm(0, sh + B_HP, sl + B_HP, sh + B_WPQ, sl + B_WPQ, qp, (int)NPROW, Hq * HDq, DPq, 0, 0, 1, 0, 1, ep0);
    run_mm(0, sh + B_HP, sl + B_HP, sh + B_WPK, sl + B_WPK, kp, (int)NPROW, HDq, DPq, 0, 0, 1, 0, 1, ep0);
    run_mm(0, sh + B_HP, sl + B_HP, sh + B_WPV, sl + B_WPV, vp, (int)NPROW, HDq, DPq, 0, 0, 1, 0, 1, ep0);
    run_mm(0, sh + B_HS, sl + B_HS, sh + B_WSQ, sl + B_WSQ, qs, (int)NSROW, Hq * HDq, DSq, 0, 0, 1, 0, 1, ep0);
    run_mm(0, sh + B_HS, sl + B_HS, sh + B_WSK, sl + B_WSK, ks, (int)NSROW, HDq, DSq, 0, 0, 1, 0, 1, ep0);
    run_mm(0, sh + B_HS, sl + B_HS, sh + B_WSV, sl + B_WSV, vs, (int)NSROW, HDq, DSq, 0, 0, 1, 0, 1, ep0);

    // 3) RoPE + layouts (emit hi/lo)
    {
        size_t tq = (size_t)Bq * NTq * Hq * (HDq / 2);
        rope_q_k<<<(int)((tq + 255) / 256), 256>>>(qp, qs, sh + B_Q, sl + B_Q);
        size_t tk = (size_t)Bq * NTq * (HDq / 2);
        rope_k_k<<<(int)((tk + 255) / 256), 256>>>(kp, ks, sh + B_K, sl + B_K);
        size_t tv = (size_t)Bq * NTq * HDq;
        transpose_v_k<<<(int)((tv + 255) / 256), 256>>>(vp, vs, sh + B_VT, sl + B_VT);
    }

    // 4) attention
    { EpiParams e = ep0; e.scale = 0.0625f;
      run_mm(1, sh + B_Q, sl + B_Q, sh + B_K, sl + B_K, sc, NTq, NTq, HDq,
             (long long)NTq * HDq, (long long)NTq * HDq, Hq,
             (long long)NTq * NTq, Bq * Hq, e); }
    softmax_split_k<<<Bq * Hq * NTq, 256>>>(sc, sh + B_SC, sl + B_SC, NTq);
    { EpiParams e = ep0; e.h0 = sh + B_AP; e.l0 = sl + B_AP; e.h1 = sh + B_AS; e.l1 = sl + B_AS;
      run_mm(2, sh + B_SC, sl + B_SC, sh + B_VT, sl + B_VT, nullptr, NTq, HDq, NTq,
             (long long)NTq * NTq, (long long)HDq * NTq, Hq, 0, Bq * Hq, e); }

    // 5) prefix: o-proj + residual, post-norm, MLP
    { EpiParams e = ep0; e.resid = prefix_x;
      run_mm(4, sh + B_AP, sl + B_AP, sh + B_WPO, sl + B_WPO, res_p, (int)NPROW, DPq, Hq * HDq, 0, 0, 1, 0, 1, e); }
    rmsnorm_split_k<<<(int)NPROW, 256>>>(res_p, p_post_ln_w, sh + B_HP2, sl + B_HP2, DPq);
    run_mm(0, sh + B_HP2, sl + B_HP2, sh + B_WPU, sl + B_WPU, Up, (int)NPROW, FPq, DPq, 0, 0, 1, 0, 1, ep0);
    { EpiParams e = ep0; e.umat = Up; e.h0 = sh + B_HPM; e.l0 = sl + B_HPM;
      run_mm(6, sh + B_HP2, sl + B_HP2, sh + B_WPG, sl + B_WPG, nullptr, (int)NPROW, FPq, DPq, 0, 0, 1, 0, 1, e); }
    { EpiParams e = ep0; e.resid = res_p;
      run_mm(4, sh + B_HPM, sl + B_HPM, sh + B_WPD, sl + B_WPD, outp, (int)NPROW, DPq, FPq, 0, 0, 1, 0, 1, e); }

    // 6) suffix: gated o-proj + residual, ada-norm2, gated MLP
    { EpiParams e = ep0; e.resid = suffix_x; e.gate = mod1 + 2 * DSq; e.ldg = 3 * DSq; e.rpb = SSq;
      run_mm(5, sh + B_AS, sl + B_AS, sh + B_WSO, sl + B_WSO, res_s, (int)NSROW, DSq, Hq * HDq, 0, 0, 1, 0, 1, e); }
    gemm_bias<<<dim3(24, 1, 1), 256>>>(cond, s_ada2_w, s_ada2_b, mod2, Bq, 3 * DSq, DCq);
    ada_norm_split_k<<<(int)NSROW, 256>>>(res_s, mod2, sh + B_H2S, sl + B_H2S, DSq, SSq);
    run_mm(0, sh + B_H2S, sl + B_H2S, sh + B_WSU, sl + B_WSU, Us, (int)NSROW, FSq, DSq, 0, 0, 1, 0, 1, ep0);
    { EpiParams e = ep0; e.umat = Us; e.h0 = sh + B_HSM; e.l0 = sl + B_HSM;
      run_mm(6, sh + B_H2S, sl + B_H2S, sh + B_WSG, sl + B_WSG, nullptr, (int)NSROW, FSq, DSq, 0, 0, 1, 0, 1, e); }
    { EpiParams e = ep0; e.resid = res_s; e.gate = mod2 + 2 * DSq; e.ldg = 3 * DSq; e.rpb = SSq;
      run_mm(5, sh + B_HSM, sl + B_HSM, sh + B_WSD, sl + B_WSD, outs, (int)NSROW, DSq, FSq, 0, 0, 1, 0, 1, e); }
}